// round 2
// baseline (speedup 1.0000x reference)
#include <cuda_runtime.h>
#include <cstdint>

#define BIGF 1e30f

// Problem constants (fixed by reference setup_inputs)
#define Bn 16
#define Cn 128
#define TA 2048
#define TB 1024
#define Rn TA   // reference timeline = modality A

// Output layout (float32, flattened in return order)
// aligned      [2,B,C,R]  offset 0            size 8388608
// aligned_mask [2,B,R]    offset 8388608      size 65536
// src_idx      [2,B,R]    offset 8454144      size 65536
// valid_ratio  [2,B]      offset 8519680      size 32
#define OFF_ALIGNED 0
#define OFF_MASK    8388608
#define OFF_IDX     8454144
#define OFF_RATIO   8519680

// -----------------------------------------------------------------------------
// Kernel 1: one warp per (b, r). Masked argmin over S source timestamps with
// JAX first-index tie-break. Writes mask (0/1) and idx (float, -1 if not ok).
// -----------------------------------------------------------------------------
__global__ __launch_bounds__(256)
void nearest_kernel(const float* __restrict__ src_t,   // [B,S]
                    const float* __restrict__ src_m,   // [B,S]
                    const float* __restrict__ ref_t,   // [B,R]
                    const float* __restrict__ ref_m,   // [B,R]
                    int S,
                    float* __restrict__ mask_out,      // [B,R]
                    float* __restrict__ idx_out)       // [B,R]
{
    int w    = (int)((blockIdx.x * blockDim.x + threadIdx.x) >> 5);
    int lane = threadIdx.x & 31;
    if (w >= Bn * Rn) return;
    int b = w / Rn;
    int r = w - b * Rn;

    float rt = ref_t[b * Rn + r];

    const float* st = src_t + (size_t)b * S;
    const float* sm = src_m + (size_t)b * S;

    float bestd = BIGF;
    int   besti = 0x7fffffff;
    // strided scan: s strictly increases per lane, so strict < preserves
    // first-index-wins within a lane
    for (int s = lane; s < S; s += 32) {
        float d = (sm[s] > 0.0f) ? fabsf(rt - st[s]) : BIGF;
        if (d < bestd) { bestd = d; besti = s; }
    }
    // warp reduction with (dist, index) lexicographic min
    #pragma unroll
    for (int off = 16; off > 0; off >>= 1) {
        float d2 = __shfl_down_sync(0xffffffffu, bestd, off);
        int   i2 = __shfl_down_sync(0xffffffffu, besti, off);
        if (d2 < bestd || (d2 == bestd && i2 < besti)) { bestd = d2; besti = i2; }
    }
    if (lane == 0) {
        // any valid source <=> bestd < BIGF (true distances are <= 100)
        bool ok = (ref_m[b * Rn + r] > 0.0f) && (bestd < BIGF);
        mask_out[b * Rn + r] = ok ? 1.0f : 0.0f;
        idx_out [b * Rn + r] = ok ? (float)besti : -1.0f;
    }
}

// -----------------------------------------------------------------------------
// Kernel 2: gather. One thread per 4 consecutive r of one (m,b,c) row.
// Reads mask/idx (L1-resident, reused 128x across c), gathers values,
// writes coalesced float4.
// -----------------------------------------------------------------------------
__global__ __launch_bounds__(256)
void gather_kernel(const float* __restrict__ vals_a,  // [B,C,TA]
                   const float* __restrict__ vals_b,  // [B,C,TB]
                   const float* __restrict__ mask,    // [2,B,R]
                   const float* __restrict__ idxf,    // [2,B,R]
                   float* __restrict__ out)           // [2,B,C,R]
{
    const int R4 = Rn / 4;
    int64_t tid = (int64_t)blockIdx.x * blockDim.x + threadIdx.x;
    // total threads = 2*Bn*Cn*R4 = 2,097,152 (exact grid)
    int r4   = (int)(tid % R4);
    int rest = (int)(tid / R4);
    int c = rest % Cn;  rest /= Cn;
    int b = rest % Bn;
    int m = rest / Bn;

    const float* vals = m ? vals_b : vals_a;
    const int    S    = m ? TB : TA;
    int mb = m * Bn + b;

    const float4 mk4 = *(const float4*)(mask + (size_t)mb * Rn + r4 * 4);
    const float4 ix4 = *(const float4*)(idxf + (size_t)mb * Rn + r4 * 4);
    const float* vrow = vals + ((size_t)b * Cn + c) * S;

    float4 o;
    o.x = (mk4.x > 0.0f) ? vrow[(int)ix4.x] : 0.0f;
    o.y = (mk4.y > 0.0f) ? vrow[(int)ix4.y] : 0.0f;
    o.z = (mk4.z > 0.0f) ? vrow[(int)ix4.z] : 0.0f;
    o.w = (mk4.w > 0.0f) ? vrow[(int)ix4.w] : 0.0f;

    *(float4*)(out + ((size_t)mb * Cn + c) * Rn + r4 * 4) = o;
}

// -----------------------------------------------------------------------------
// Kernel 3: valid_ratio = mean over R of mask, one block per (m,b).
// Fixed-order tree reduction (deterministic; sums of k/2048 are exact in fp32).
// -----------------------------------------------------------------------------
__global__ __launch_bounds__(256)
void ratio_kernel(const float* __restrict__ mask,  // [2,B,R]
                  float* __restrict__ ratio)       // [2,B]
{
    __shared__ float sred[256];
    int mb = blockIdx.x;
    float acc = 0.0f;
    for (int r = threadIdx.x; r < Rn; r += 256)
        acc += mask[(size_t)mb * Rn + r];
    sred[threadIdx.x] = acc;
    __syncthreads();
    for (int s = 128; s > 0; s >>= 1) {
        if (threadIdx.x < s) sred[threadIdx.x] += sred[threadIdx.x + s];
        __syncthreads();
    }
    if (threadIdx.x == 0)
        ratio[mb] = sred[0] * (1.0f / (float)Rn);
}

extern "C" void kernel_launch(void* const* d_in, const int* in_sizes, int n_in,
                              void* d_out, int out_size)
{
    const float* values_a     = (const float*)d_in[0];
    const float* timestamps_a = (const float*)d_in[1];
    const float* masks_a      = (const float*)d_in[2];
    const float* values_b     = (const float*)d_in[3];
    const float* timestamps_b = (const float*)d_in[4];
    const float* masks_b      = (const float*)d_in[5];
    float* out = (float*)d_out;

    float* aligned = out + OFF_ALIGNED;
    float* maskout = out + OFF_MASK;   // [2,B,R]
    float* idxout  = out + OFF_IDX;    // [2,B,R]
    float* ratio   = out + OFF_RATIO;  // [2,B]

    // Phase 1: nearest-index argmin, one warp per (b,r). 65536/8 warps/block.
    {
        int warps  = Bn * Rn;                 // 32768 per modality
        int blocks = (warps * 32 + 255) / 256;
        // modality A aligned to A's own timeline
        nearest_kernel<<<blocks, 256>>>(timestamps_a, masks_a,
                                        timestamps_a, masks_a, TA,
                                        maskout + 0 * Bn * Rn,
                                        idxout  + 0 * Bn * Rn);
        // modality B aligned to A's timeline
        nearest_kernel<<<blocks, 256>>>(timestamps_b, masks_b,
                                        timestamps_a, masks_a, TB,
                                        maskout + 1 * Bn * Rn,
                                        idxout  + 1 * Bn * Rn);
    }

    // Phase 2: gather -> aligned [2,B,C,R]
    {
        int64_t total = (int64_t)2 * Bn * Cn * (Rn / 4); // 2,097,152
        int blocks = (int)((total + 255) / 256);         // 8192
        gather_kernel<<<blocks, 256>>>(values_a, values_b, maskout, idxout, aligned);
    }

    // Phase 3: valid_ratio [2,B]
    ratio_kernel<<<2 * Bn, 256>>>(maskout, ratio);

    (void)in_sizes; (void)n_in; (void)out_size;
}

// round 4
// speedup vs baseline: 2.9254x; 2.9254x over previous
#include <cuda_runtime.h>
#include <cstdint>

// Problem constants (fixed by reference setup_inputs)
#define Bn 16
#define Cn 128
#define TA 2048
#define TB 1024
#define Rn TA   // reference timeline = modality A

// Output layout (float32, flattened in return order)
#define OFF_ALIGNED 0
#define OFF_MASK    8388608
#define OFF_IDX     8454144
#define OFF_RATIO   8519680

// -----------------------------------------------------------------------------
// Kernel 1: nearest-valid-source via compaction + binary search.
// Grid: 128 blocks of 256 threads. blockIdx.x -> (m, b, r-chunk of 512 refs).
// Each block compacts the valid sources of its (m,b) row into smem
// (order-preserving, so compacted position order == original index order,
// and timestamps stay sorted), then binary-searches each reference timestamp.
// Tie-break rules (JAX argmin = first index):
//   - left candidate uses lower_bound of its timestamp -> first duplicate
//   - on equal distance, left wins (its position < lo, i.e. smaller index)
// -----------------------------------------------------------------------------
__global__ __launch_bounds__(256)
void nearest_kernel(const float* __restrict__ ta, const float* __restrict__ ma,  // A: t,m [B,TA]
                    const float* __restrict__ tb, const float* __restrict__ mb_, // B: t,m [B,TB]
                    float* __restrict__ mask_out,  // [2,B,R]
                    float* __restrict__ idx_out)   // [2,B,R]
{
    __shared__ float comp_t[TA];
    __shared__ int   comp_i[TA];
    __shared__ int   scan[256];

    const int t     = threadIdx.x;
    const int chunk = blockIdx.x & 3;          // which 512-ref chunk
    const int mb    = blockIdx.x >> 2;         // 0..31
    const int m     = mb >> 4;
    const int b     = mb & 15;
    const int S     = m ? TB : TA;

    const float* src_t = (m ? tb : ta) + (size_t)b * S;
    const float* src_m = (m ? mb_ : ma) + (size_t)b * S;
    const float* ref_t = ta + (size_t)b * Rn;
    const float* ref_m = ma + (size_t)b * Rn;

    // ---- order-preserving compaction of valid sources ----
    const int per  = S >> 8;                   // 8 (A) or 4 (B)
    const int base = t * per;
    int cnt = 0;
    #pragma unroll 8
    for (int i = 0; i < per; i++)
        cnt += (src_m[base + i] > 0.0f) ? 1 : 0;
    scan[t] = cnt;
    __syncthreads();
    // Hillis-Steele inclusive scan over 256 thread counts
    #pragma unroll
    for (int off = 1; off < 256; off <<= 1) {
        int v = (t >= off) ? scan[t - off] : 0;
        __syncthreads();
        scan[t] += v;
        __syncthreads();
    }
    int pos = scan[t] - cnt;                   // exclusive prefix
    for (int i = 0; i < per; i++) {
        int s = base + i;
        if (src_m[s] > 0.0f) {
            comp_t[pos] = src_t[s];
            comp_i[pos] = s;
            pos++;
        }
    }
    __syncthreads();
    const int nv = scan[255];

    // ---- binary search per reference point (512 refs per block, 2/thread) ----
    float* mo = mask_out + (size_t)mb * Rn;
    float* io = idx_out  + (size_t)mb * Rn;

    #pragma unroll
    for (int it = 0; it < 2; it++) {
        int r = chunk * 512 + it * 256 + t;
        float rt = ref_t[r];
        bool ok = (ref_m[r] > 0.0f) && (nv > 0);
        int idx = -1;
        if (ok) {
            // lower_bound: first position with comp_t[pos] >= rt
            int lo = 0, hi = nv;
            while (lo < hi) {
                int mid = (lo + hi) >> 1;
                if (comp_t[mid] < rt) lo = mid + 1; else hi = mid;
            }
            if (lo == 0) {
                idx = comp_i[0];                       // only right candidate
            } else {
                float tl = comp_t[lo - 1];
                bool take_left = (lo == nv);
                if (!take_left) {
                    float dl = rt - tl;                // > 0 by lower_bound
                    float dr = comp_t[lo] - rt;        // >= 0
                    take_left = (dl <= dr);            // tie -> left (smaller idx)
                }
                if (take_left) {
                    // first occurrence of tl (duplicate-timestamp tie-break)
                    int l2 = 0, h2 = lo - 1;           // comp_t[lo-1]==tl -> result<=lo-1
                    while (l2 < h2) {
                        int mid = (l2 + h2) >> 1;
                        if (comp_t[mid] < tl) l2 = mid + 1; else h2 = mid;
                    }
                    idx = comp_i[l2];
                } else {
                    idx = comp_i[lo];                  // lo is first occurrence of its value
                }
            }
        }
        mo[r] = ok ? 1.0f : 0.0f;
        io[r] = ok ? (float)idx : -1.0f;
    }
}

// -----------------------------------------------------------------------------
// Kernel 2: gather. One thread per 4 consecutive r of one (m,b,c) row.
// idx < 0 encodes invalid (no separate mask read). Coalesced float4 writes;
// gather reads are near-sequential (nearest index is monotone in r).
// -----------------------------------------------------------------------------
__global__ __launch_bounds__(256)
void gather_kernel(const float* __restrict__ vals_a,  // [B,C,TA]
                   const float* __restrict__ vals_b,  // [B,C,TB]
                   const float* __restrict__ idxf,    // [2,B,R]
                   float* __restrict__ out)           // [2,B,C,R]
{
    const int R4 = Rn / 4;
    int64_t tid = (int64_t)blockIdx.x * blockDim.x + threadIdx.x;
    int r4   = (int)(tid % R4);
    int rest = (int)(tid / R4);
    int c = rest % Cn;  rest /= Cn;
    int b = rest % Bn;
    int m = rest / Bn;

    const float* vals = m ? vals_b : vals_a;
    const int    S    = m ? TB : TA;
    int mb = m * Bn + b;

    const float4 ix4 = *(const float4*)(idxf + (size_t)mb * Rn + r4 * 4);
    const float* vrow = vals + ((size_t)b * Cn + c) * S;

    float4 o;
    o.x = (ix4.x >= 0.0f) ? vrow[(int)ix4.x] : 0.0f;
    o.y = (ix4.y >= 0.0f) ? vrow[(int)ix4.y] : 0.0f;
    o.z = (ix4.z >= 0.0f) ? vrow[(int)ix4.z] : 0.0f;
    o.w = (ix4.w >= 0.0f) ? vrow[(int)ix4.w] : 0.0f;

    *(float4*)(out + ((size_t)mb * Cn + c) * Rn + r4 * 4) = o;
}

// -----------------------------------------------------------------------------
// Kernel 3: valid_ratio = mean over R of mask, one block per (m,b).
// Fixed-order tree reduction (deterministic; sums of k/2048 exact in fp32).
// -----------------------------------------------------------------------------
__global__ __launch_bounds__(256)
void ratio_kernel(const float* __restrict__ mask,  // [2,B,R]
                  float* __restrict__ ratio)       // [2,B]
{
    __shared__ float sred[256];
    int mb = blockIdx.x;
    float acc = 0.0f;
    for (int r = threadIdx.x; r < Rn; r += 256)
        acc += mask[(size_t)mb * Rn + r];
    sred[threadIdx.x] = acc;
    __syncthreads();
    for (int s = 128; s > 0; s >>= 1) {
        if (threadIdx.x < s) sred[threadIdx.x] += sred[threadIdx.x + s];
        __syncthreads();
    }
    if (threadIdx.x == 0)
        ratio[mb] = sred[0] * (1.0f / (float)Rn);
}

extern "C" void kernel_launch(void* const* d_in, const int* in_sizes, int n_in,
                              void* d_out, int out_size)
{
    const float* values_a     = (const float*)d_in[0];
    const float* timestamps_a = (const float*)d_in[1];
    const float* masks_a      = (const float*)d_in[2];
    const float* values_b     = (const float*)d_in[3];
    const float* timestamps_b = (const float*)d_in[4];
    const float* masks_b      = (const float*)d_in[5];
    float* out = (float*)d_out;

    float* aligned = out + OFF_ALIGNED;
    float* maskout = out + OFF_MASK;   // [2,B,R]
    float* idxout  = out + OFF_IDX;    // [2,B,R]
    float* ratio   = out + OFF_RATIO;  // [2,B]

    // Phase 1: compaction + binary-search nearest index. 128 blocks.
    nearest_kernel<<<128, 256>>>(timestamps_a, masks_a,
                                 timestamps_b, masks_b,
                                 maskout, idxout);

    // Phase 2: gather -> aligned [2,B,C,R]
    {
        int64_t total = (int64_t)2 * Bn * Cn * (Rn / 4); // 2,097,152 threads
        int blocks = (int)((total + 255) / 256);         // 8192
        gather_kernel<<<blocks, 256>>>(values_a, values_b, idxout, aligned);
    }

    // Phase 3: valid_ratio [2,B]
    ratio_kernel<<<2 * Bn, 256>>>(maskout, ratio);

    (void)in_sizes; (void)n_in; (void)out_size;
}

// round 7
// speedup vs baseline: 2.9660x; 1.0139x over previous
#include <cuda_runtime.h>
#include <cstdint>

// Problem constants (fixed by reference setup_inputs)
#define Bn 16
#define Cn 128
#define TA 2048
#define TB 1024
#define Rn TA   // reference timeline = modality A

// Output layout (float32, flattened in return order)
#define OFF_ALIGNED 0
#define OFF_MASK    8388608
#define OFF_IDX     8454144
#define OFF_RATIO   8519680

// Scratch: compacted valid sources per (m,b) row. 32 rows x 2048 max.
__device__ float d_comp_t[32 * 2048];
__device__ int   d_comp_i[32 * 2048];
__device__ int   d_nv[32];

// -----------------------------------------------------------------------------
// Kernel 1: order-preserving compaction of valid sources, one block per (m,b).
// Shuffle-based block scan (2 barriers). Writes compacted timestamps/indices
// (still sorted, original-index order) and the valid count nv.
// -----------------------------------------------------------------------------
__global__ __launch_bounds__(256)
void compact_kernel(const float* __restrict__ ta, const float* __restrict__ ma,
                    const float* __restrict__ tb, const float* __restrict__ mb_)
{
    const int t  = threadIdx.x;
    const int mb = blockIdx.x;            // 0..31
    const int m  = mb >> 4;
    const int b  = mb & 15;
    const int S  = m ? TB : TA;

    const float* src_t = (m ? tb : ta) + (size_t)b * S;
    const float* src_m = (m ? mb_ : ma) + (size_t)b * S;

    const int per  = S >> 8;              // 8 (A) or 4 (B)
    const int base = t * per;

    int cnt = 0;
    for (int i = 0; i < per; i++)
        cnt += (src_m[base + i] > 0.0f) ? 1 : 0;

    // block-wide scan: warp shuffle scan + warp-total scan
    const int lane = t & 31, wid = t >> 5;
    int inc = cnt;
    #pragma unroll
    for (int off = 1; off < 32; off <<= 1) {
        int v = __shfl_up_sync(0xffffffffu, inc, off);
        if (lane >= off) inc += v;
    }
    __shared__ int wtot[8], woff[8];
    if (lane == 31) wtot[wid] = inc;
    __syncthreads();
    if (t < 8) {
        int v = wtot[t];
        int s = v;
        #pragma unroll
        for (int off = 1; off < 8; off <<= 1) {
            int u = __shfl_up_sync(0x000000ffu, s, off);
            if (t >= off) s += u;
        }
        woff[t] = s - v;                  // exclusive warp offset
        if (t == 7) d_nv[mb] = s;         // total valid count
    }
    __syncthreads();

    int pos = woff[wid] + inc - cnt;      // exclusive prefix for this thread
    float* ct = d_comp_t + mb * 2048;
    int*   ci = d_comp_i + mb * 2048;
    for (int i = 0; i < per; i++) {
        int s = base + i;
        if (src_m[s] > 0.0f) {            // re-read hits L1
            ct[pos] = src_t[s];
            ci[pos] = s;
            pos++;
        }
    }
}

// -----------------------------------------------------------------------------
// Kernel 2: binary search per reference point. 256 blocks: (m,b) x 8 chunks
// of 256 refs, 1 ref/thread. Compacted timestamps staged in smem.
// Tie-break (JAX argmin = first index):
//   - equal distance -> left neighbor (smaller original index)
//   - duplicate timestamps -> walk back to first occurrence (O(1) expected)
// Also writes valid_ratio (chunk 0, thread 0): ratio = (nv>0 ? nvA : 0)/2048.
// -----------------------------------------------------------------------------
__global__ __launch_bounds__(256)
void search_kernel(const float* __restrict__ ta, const float* __restrict__ ma,
                   float* __restrict__ mask_out,  // [2,B,R]
                   float* __restrict__ idx_out,   // [2,B,R]
                   float* __restrict__ ratio)     // [2,B]
{
    __shared__ float s_t[2048];
    const int t     = threadIdx.x;
    const int chunk = blockIdx.x & 7;
    const int mb    = blockIdx.x >> 3;
    const int b     = mb & 15;

    const int nv = d_nv[mb];
    const float* ct = d_comp_t + mb * 2048;
    const int*   ci = d_comp_i + mb * 2048;

    for (int i = t; i < nv; i += 256) s_t[i] = ct[i];
    __syncthreads();

    const int r = chunk * 256 + t;
    const float rt = ta[(size_t)b * Rn + r];
    const bool ok = (ma[(size_t)b * Rn + r] > 0.0f) && (nv > 0);

    int idx = -1;
    if (ok) {
        // lower_bound: first position with s_t[pos] >= rt
        int lo = 0, hi = nv;
        while (lo < hi) {
            int mid = (lo + hi) >> 1;
            if (s_t[mid] < rt) lo = mid + 1; else hi = mid;
        }
        int p;
        if (lo == 0) {
            p = 0;                                      // only right candidate
        } else if (lo == nv || (rt - s_t[lo - 1]) <= (s_t[lo] - rt)) {
            float tl = s_t[lo - 1];
            p = lo - 1;
            while (p > 0 && s_t[p - 1] == tl) p--;      // first duplicate
        } else {
            p = lo;                                     // lo is first occurrence
        }
        idx = __ldg(ci + p);                            // L2 hit
    }
    mask_out[(size_t)mb * Rn + r] = ok ? 1.0f : 0.0f;
    idx_out [(size_t)mb * Rn + r] = ok ? (float)idx : -1.0f;

    if (chunk == 0 && t == 0) {
        // ok[r] = (ref valid) && (nv>0); ref validity == modality-A validity,
        // so sum over r of ok = (nv>0 ? nv_A[b] : 0). Exact k/2048 in fp32.
        int nvA = d_nv[b];
        ratio[mb] = (nv > 0 ? (float)nvA : 0.0f) * (1.0f / (float)Rn);
    }
}

// -----------------------------------------------------------------------------
// Kernel 3: gather. One thread per 4 consecutive r of one (m,b,c) row.
// idx < 0 encodes invalid. Coalesced float4 writes; gather reads are
// near-sequential (nearest index is monotone in r). DRAM-bound.
// -----------------------------------------------------------------------------
__global__ __launch_bounds__(256)
void gather_kernel(const float* __restrict__ vals_a,  // [B,C,TA]
                   const float* __restrict__ vals_b,  // [B,C,TB]
                   const float* __restrict__ idxf,    // [2,B,R]
                   float* __restrict__ out)           // [2,B,C,R]
{
    const int R4 = Rn / 4;
    int64_t tid = (int64_t)blockIdx.x * blockDim.x + threadIdx.x;
    int r4   = (int)(tid % R4);
    int rest = (int)(tid / R4);
    int c = rest % Cn;  rest /= Cn;
    int b = rest % Bn;
    int m = rest / Bn;

    const float* vals = m ? vals_b : vals_a;
    const int    S    = m ? TB : TA;
    int mb = m * Bn + b;

    const float4 ix4 = __ldg((const float4*)(idxf + (size_t)mb * Rn + r4 * 4));
    const float* vrow = vals + ((size_t)b * Cn + c) * S;

    float4 o;
    o.x = (ix4.x >= 0.0f) ? __ldg(vrow + (int)ix4.x) : 0.0f;
    o.y = (ix4.y >= 0.0f) ? __ldg(vrow + (int)ix4.y) : 0.0f;
    o.z = (ix4.z >= 0.0f) ? __ldg(vrow + (int)ix4.z) : 0.0f;
    o.w = (ix4.w >= 0.0f) ? __ldg(vrow + (int)ix4.w) : 0.0f;

    *(float4*)(out + ((size_t)mb * Cn + c) * Rn + r4 * 4) = o;
}

extern "C" void kernel_launch(void* const* d_in, const int* in_sizes, int n_in,
                              void* d_out, int out_size)
{
    const float* values_a     = (const float*)d_in[0];
    const float* timestamps_a = (const float*)d_in[1];
    const float* masks_a      = (const float*)d_in[2];
    const float* values_b     = (const float*)d_in[3];
    const float* timestamps_b = (const float*)d_in[4];
    const float* masks_b      = (const float*)d_in[5];
    float* out = (float*)d_out;

    float* aligned = out + OFF_ALIGNED;
    float* maskout = out + OFF_MASK;   // [2,B,R]
    float* idxout  = out + OFF_IDX;    // [2,B,R]
    float* ratio   = out + OFF_RATIO;  // [2,B]

    // Phase 1a: compact valid sources (32 blocks, one per (m,b))
    compact_kernel<<<32, 256>>>(timestamps_a, masks_a, timestamps_b, masks_b);

    // Phase 1b: binary-search nearest index + ratio (256 blocks)
    search_kernel<<<256, 256>>>(timestamps_a, masks_a, maskout, idxout, ratio);

    // Phase 2: gather -> aligned [2,B,C,R] (DRAM-bound)
    {
        int64_t total = (int64_t)2 * Bn * Cn * (Rn / 4); // 2,097,152 threads
        int blocks = (int)((total + 255) / 256);         // 8192
        gather_kernel<<<blocks, 256>>>(values_a, values_b, idxout, aligned);
    }

    (void)in_sizes; (void)n_in; (void)out_size;
}

// round 9
// speedup vs baseline: 3.6962x; 1.2462x over previous
#include <cuda_runtime.h>
#include <cstdint>

// Problem constants (fixed by reference setup_inputs)
#define Bn 16
#define Cn 128
#define TA 2048
#define TB 1024
#define Rn TA   // reference timeline = modality A

// Output layout (float32, flattened in return order)
#define OFF_ALIGNED 0
#define OFF_MASK    8388608
#define OFF_IDX     8454144
#define OFF_RATIO   8519680

// -----------------------------------------------------------------------------
// Kernel 1 (fused): per-block redundant compaction + binary search + ratio.
// Grid: 256 blocks of 256 threads. blockIdx.x -> (mb = m*16+b, chunk of 256 refs).
// Each block compacts the valid sources of its (m,b) row into smem
// (order-preserving: compacted order == original index order, timestamps
// stay sorted), then binary-searches its 256 reference timestamps.
// Tie-break (JAX argmin = first index):
//   - equal distance -> left neighbor (smaller original index)
//   - duplicate timestamps -> walk back to first occurrence (O(1) expected)
// chunk-0 blocks also write valid_ratio[mb] = (nv>0 ? nvA : 0)/2048 (exact).
// -----------------------------------------------------------------------------
__global__ __launch_bounds__(256)
void align_kernel(const float* __restrict__ ta, const float* __restrict__ ma,  // A t,m [B,TA]
                  const float* __restrict__ tb, const float* __restrict__ mb_, // B t,m [B,TB]
                  float* __restrict__ mask_out,  // [2,B,R]
                  float* __restrict__ idx_out,   // [2,B,R]
                  float* __restrict__ ratio)     // [2,B]
{
    __shared__ float s_t[2048];
    __shared__ int   s_i[2048];
    __shared__ int   wtot[8], woff[8];
    __shared__ int   s_nvA;

    const int t     = threadIdx.x;
    const int chunk = blockIdx.x & 7;
    const int mb    = blockIdx.x >> 3;    // 0..31
    const int m     = mb >> 4;
    const int b     = mb & 15;
    const int S     = m ? TB : TA;

    const float* src_t = (m ? tb : ta) + (size_t)b * S;
    const float* src_m = (m ? mb_ : ma) + (size_t)b * S;

    // ---- order-preserving compaction into smem ----
    const int per  = S >> 8;              // 8 (A) or 4 (B)
    const int base = t * per;
    const int lane = t & 31, wid = t >> 5;

    float v_t[8];
    float v_m[8];
    #pragma unroll
    for (int i = 0; i < 8; i++) {
        if (i < per) {
            v_t[i] = src_t[base + i];
            v_m[i] = src_m[base + i];
        }
    }
    int cnt = 0;
    #pragma unroll
    for (int i = 0; i < 8; i++)
        if (i < per) cnt += (v_m[i] > 0.0f) ? 1 : 0;

    // block scan: warp shuffle scan + warp-total scan
    int inc = cnt;
    #pragma unroll
    for (int off = 1; off < 32; off <<= 1) {
        int v = __shfl_up_sync(0xffffffffu, inc, off);
        if (lane >= off) inc += v;
    }
    if (lane == 31) wtot[wid] = inc;
    __syncthreads();
    if (t < 8) {
        int v = wtot[t];
        int s = v;
        #pragma unroll
        for (int off = 1; off < 8; off <<= 1) {
            int u = __shfl_up_sync(0x000000ffu, s, off);
            if (t >= off) s += u;
        }
        woff[t] = s - v;                  // exclusive warp offset
    }
    __syncthreads();

    int pos = woff[wid] + inc - cnt;      // exclusive prefix for this thread
    #pragma unroll
    for (int i = 0; i < 8; i++) {
        if (i < per && v_m[i] > 0.0f) {
            s_t[pos] = v_t[i];
            s_i[pos] = base + i;
            pos++;
        }
    }
    const int nv = woff[7] + wtot[7];     // total valid count
    __syncthreads();

    // ---- binary search: 256 refs per block, one per thread ----
    const int r = chunk * 256 + t;
    const float rt = ta[(size_t)b * Rn + r];
    const bool ok = (ma[(size_t)b * Rn + r] > 0.0f) && (nv > 0);

    int idx = -1;
    if (ok) {
        int lo = 0, hi = nv;              // lower_bound: first s_t[pos] >= rt
        while (lo < hi) {
            int mid = (lo + hi) >> 1;
            if (s_t[mid] < rt) lo = mid + 1; else hi = mid;
        }
        int p;
        if (lo == 0) {
            p = 0;                                      // only right candidate
        } else if (lo == nv || (rt - s_t[lo - 1]) <= (s_t[lo] - rt)) {
            float tl = s_t[lo - 1];
            p = lo - 1;
            while (p > 0 && s_t[p - 1] == tl) p--;      // first duplicate
        } else {
            p = lo;                                     // lo is first occurrence
        }
        idx = s_i[p];
    }
    mask_out[(size_t)mb * Rn + r] = ok ? 1.0f : 0.0f;
    idx_out [(size_t)mb * Rn + r] = ok ? (float)idx : -1.0f;

    // ---- valid_ratio (chunk-0 blocks only) ----
    if (chunk == 0) {
        // ratio[m,b] = (nv>0 ? nvA : 0) / 2048, nvA = #valid in masks_a[b].
        // For m==0, nvA == nv. For m==1, count it (2048 L2-hit loads).
        if (m == 0) {
            if (t == 0)
                ratio[mb] = (nv > 0 ? (float)nv : 0.0f) * (1.0f / (float)Rn);
        } else {
            if (t == 0) s_nvA = 0;
            __syncthreads();
            const float* am = ma + (size_t)b * TA;
            int c2 = 0;
            #pragma unroll
            for (int i = 0; i < 8; i++)
                c2 += (am[t * 8 + i] > 0.0f) ? 1 : 0;
            #pragma unroll
            for (int off = 16; off > 0; off >>= 1)
                c2 += __shfl_down_sync(0xffffffffu, c2, off);
            if (lane == 0) atomicAdd(&s_nvA, c2);
            __syncthreads();
            if (t == 0)
                ratio[mb] = (nv > 0 ? (float)s_nvA : 0.0f) * (1.0f / (float)Rn);
        }
    }
}

// -----------------------------------------------------------------------------
// Kernel 2: gather. One thread per 4 consecutive r of one (m,b,c) row.
// idx < 0 encodes invalid. Coalesced float4 writes; gather reads are
// near-sequential (nearest index is monotone in r). DRAM-bound.
// -----------------------------------------------------------------------------
__global__ __launch_bounds__(256)
void gather_kernel(const float* __restrict__ vals_a,  // [B,C,TA]
                   const float* __restrict__ vals_b,  // [B,C,TB]
                   const float* __restrict__ idxf,    // [2,B,R]
                   float* __restrict__ out)           // [2,B,C,R]
{
    const int R4 = Rn / 4;
    int64_t tid = (int64_t)blockIdx.x * blockDim.x + threadIdx.x;
    int r4   = (int)(tid % R4);
    int rest = (int)(tid / R4);
    int c = rest % Cn;  rest /= Cn;
    int b = rest % Bn;
    int m = rest / Bn;

    const float* vals = m ? vals_b : vals_a;
    const int    S    = m ? TB : TA;
    int mb = m * Bn + b;

    const float4 ix4 = __ldg((const float4*)(idxf + (size_t)mb * Rn + r4 * 4));
    const float* vrow = vals + ((size_t)b * Cn + c) * S;

    float4 o;
    o.x = (ix4.x >= 0.0f) ? __ldg(vrow + (int)ix4.x) : 0.0f;
    o.y = (ix4.y >= 0.0f) ? __ldg(vrow + (int)ix4.y) : 0.0f;
    o.z = (ix4.z >= 0.0f) ? __ldg(vrow + (int)ix4.z) : 0.0f;
    o.w = (ix4.w >= 0.0f) ? __ldg(vrow + (int)ix4.w) : 0.0f;

    *(float4*)(out + ((size_t)mb * Cn + c) * Rn + r4 * 4) = o;
}

extern "C" void kernel_launch(void* const* d_in, const int* in_sizes, int n_in,
                              void* d_out, int out_size)
{
    const float* values_a     = (const float*)d_in[0];
    const float* timestamps_a = (const float*)d_in[1];
    const float* masks_a      = (const float*)d_in[2];
    const float* values_b     = (const float*)d_in[3];
    const float* timestamps_b = (const float*)d_in[4];
    const float* masks_b      = (const float*)d_in[5];
    float* out = (float*)d_out;

    float* aligned = out + OFF_ALIGNED;
    float* maskout = out + OFF_MASK;   // [2,B,R]
    float* idxout  = out + OFF_IDX;    // [2,B,R]
    float* ratio   = out + OFF_RATIO;  // [2,B]

    // Phase 1: fused compaction + search + ratio (256 blocks)
    align_kernel<<<256, 256>>>(timestamps_a, masks_a, timestamps_b, masks_b,
                               maskout, idxout, ratio);

    // Phase 2: gather -> aligned [2,B,C,R] (DRAM-bound)
    {
        int64_t total = (int64_t)2 * Bn * Cn * (Rn / 4); // 2,097,152 threads
        int blocks = (int)((total + 255) / 256);         // 8192
        gather_kernel<<<blocks, 256>>>(values_a, values_b, idxout, aligned);
    }

    (void)in_sizes; (void)n_in; (void)out_size;
}

// round 10
// speedup vs baseline: 4.2902x; 1.1607x over previous
#include <cuda_runtime.h>
#include <cstdint>

// Problem constants (fixed by reference setup_inputs)
#define Bn 16
#define Cn 128
#define TA 2048
#define TB 1024
#define Rn TA   // reference timeline = modality A
#define GC 8    // channels per gather thread

// Output layout (float32, flattened in return order)
#define OFF_ALIGNED 0
#define OFF_MASK    8388608
#define OFF_IDX     8454144
#define OFF_RATIO   8519680

// Integer copy of the nearest-index table (avoids float->int cvt in gather)
__device__ int d_idxi[32 * 2048];

// -----------------------------------------------------------------------------
// Kernel 1 (fused): per-block redundant compaction + binary search + ratio.
// Grid: 256 blocks of 256 threads. blockIdx.x -> (mb = m*16+b, chunk of 256 refs).
// -----------------------------------------------------------------------------
__global__ __launch_bounds__(256)
void align_kernel(const float* __restrict__ ta, const float* __restrict__ ma,  // A t,m [B,TA]
                  const float* __restrict__ tb, const float* __restrict__ mb_, // B t,m [B,TB]
                  float* __restrict__ mask_out,  // [2,B,R]
                  float* __restrict__ idx_out,   // [2,B,R]
                  float* __restrict__ ratio)     // [2,B]
{
    __shared__ float s_t[2048];
    __shared__ int   s_i[2048];
    __shared__ int   wtot[8], woff[8];
    __shared__ int   s_nvA;

    const int t     = threadIdx.x;
    const int chunk = blockIdx.x & 7;
    const int mb    = blockIdx.x >> 3;    // 0..31
    const int m     = mb >> 4;
    const int b     = mb & 15;
    const int S     = m ? TB : TA;

    const float* src_t = (m ? tb : ta) + (size_t)b * S;
    const float* src_m = (m ? mb_ : ma) + (size_t)b * S;

    // ---- order-preserving compaction into smem ----
    const int per  = S >> 8;              // 8 (A) or 4 (B)
    const int base = t * per;
    const int lane = t & 31, wid = t >> 5;

    float v_t[8];
    float v_m[8];
    #pragma unroll
    for (int i = 0; i < 8; i++) {
        if (i < per) {
            v_t[i] = src_t[base + i];
            v_m[i] = src_m[base + i];
        }
    }
    int cnt = 0;
    #pragma unroll
    for (int i = 0; i < 8; i++)
        if (i < per) cnt += (v_m[i] > 0.0f) ? 1 : 0;

    // block scan: warp shuffle scan + warp-total scan
    int inc = cnt;
    #pragma unroll
    for (int off = 1; off < 32; off <<= 1) {
        int v = __shfl_up_sync(0xffffffffu, inc, off);
        if (lane >= off) inc += v;
    }
    if (lane == 31) wtot[wid] = inc;
    __syncthreads();
    if (t < 8) {
        int v = wtot[t];
        int s = v;
        #pragma unroll
        for (int off = 1; off < 8; off <<= 1) {
            int u = __shfl_up_sync(0x000000ffu, s, off);
            if (t >= off) s += u;
        }
        woff[t] = s - v;                  // exclusive warp offset
    }
    __syncthreads();

    int pos = woff[wid] + inc - cnt;      // exclusive prefix for this thread
    #pragma unroll
    for (int i = 0; i < 8; i++) {
        if (i < per && v_m[i] > 0.0f) {
            s_t[pos] = v_t[i];
            s_i[pos] = base + i;
            pos++;
        }
    }
    const int nv = woff[7] + wtot[7];     // total valid count
    __syncthreads();

    // ---- binary search: 256 refs per block, one per thread ----
    const int r = chunk * 256 + t;
    const float rt = ta[(size_t)b * Rn + r];
    const bool ok = (ma[(size_t)b * Rn + r] > 0.0f) && (nv > 0);

    int idx = -1;
    if (ok) {
        int lo = 0, hi = nv;              // lower_bound: first s_t[pos] >= rt
        while (lo < hi) {
            int mid = (lo + hi) >> 1;
            if (s_t[mid] < rt) lo = mid + 1; else hi = mid;
        }
        int p;
        if (lo == 0) {
            p = 0;                                      // only right candidate
        } else if (lo == nv || (rt - s_t[lo - 1]) <= (s_t[lo] - rt)) {
            float tl = s_t[lo - 1];
            p = lo - 1;
            while (p > 0 && s_t[p - 1] == tl) p--;      // first duplicate
        } else {
            p = lo;                                     // lo is first occurrence
        }
        idx = s_i[p];
    }
    mask_out[(size_t)mb * Rn + r] = ok ? 1.0f : 0.0f;
    idx_out [(size_t)mb * Rn + r] = ok ? (float)idx : -1.0f;
    d_idxi  [(size_t)mb * Rn + r] = ok ? idx : -1;

    // ---- valid_ratio (chunk-0 blocks only) ----
    if (chunk == 0) {
        // ratio[m,b] = (nv>0 ? nvA : 0) / 2048, nvA = #valid in masks_a[b].
        if (m == 0) {
            if (t == 0)
                ratio[mb] = (nv > 0 ? (float)nv : 0.0f) * (1.0f / (float)Rn);
        } else {
            if (t == 0) s_nvA = 0;
            __syncthreads();
            const float* am = ma + (size_t)b * TA;
            int c2 = 0;
            #pragma unroll
            for (int i = 0; i < 8; i++)
                c2 += (am[t * 8 + i] > 0.0f) ? 1 : 0;
            #pragma unroll
            for (int off = 16; off > 0; off >>= 1)
                c2 += __shfl_down_sync(0xffffffffu, c2, off);
            if (lane == 0) atomicAdd(&s_nvA, c2);
            __syncthreads();
            if (t == 0)
                ratio[mb] = (nv > 0 ? (float)s_nvA : 0.0f) * (1.0f / (float)Rn);
        }
    }
}

// -----------------------------------------------------------------------------
// Kernel 2: gather. One thread serves GC=8 channels of one (m,b) with the same
// int4 index vector (idx depends only on (m,b,r)). Per thread: one int4 idx
// load, then 8x (4 gathers + 1 float4 store), fully unrolled for MLP.
// grid: mb(32) x ctile(16) x rtile(2) = 1024 blocks of 256 threads.
// -----------------------------------------------------------------------------
__global__ __launch_bounds__(256)
void gather_kernel(const float* __restrict__ vals_a,  // [B,C,TA]
                   const float* __restrict__ vals_b,  // [B,C,TB]
                   float* __restrict__ out)           // [2,B,C,R]
{
    const int bid   = blockIdx.x;
    const int rtile = bid & 1;
    const int ctile = (bid >> 1) & 15;
    const int mb    = bid >> 5;           // 0..31
    const int m     = mb >> 4;
    const int b     = mb & 15;
    const int S     = m ? TB : TA;
    const float* vals = m ? vals_b : vals_a;

    const int r4 = rtile * 256 + threadIdx.x;   // 0..511 (float4 granules of r)

    const int4 ix = __ldg((const int4*)(d_idxi + (size_t)mb * Rn) + r4);
    const bool vx = ix.x >= 0, vy = ix.y >= 0, vz = ix.z >= 0, vw = ix.w >= 0;

    const float* vbase = vals + ((size_t)b * Cn + ctile * GC) * S;
    float*       obase = out  + ((size_t)mb * Cn + ctile * GC) * Rn + r4 * 4;

    #pragma unroll
    for (int c = 0; c < GC; c++) {
        const float* vrow = vbase + (size_t)c * S;
        float4 o;
        o.x = vx ? __ldg(vrow + ix.x) : 0.0f;
        o.y = vy ? __ldg(vrow + ix.y) : 0.0f;
        o.z = vz ? __ldg(vrow + ix.z) : 0.0f;
        o.w = vw ? __ldg(vrow + ix.w) : 0.0f;
        *(float4*)(obase + (size_t)c * Rn) = o;
    }
}

extern "C" void kernel_launch(void* const* d_in, const int* in_sizes, int n_in,
                              void* d_out, int out_size)
{
    const float* values_a     = (const float*)d_in[0];
    const float* timestamps_a = (const float*)d_in[1];
    const float* masks_a      = (const float*)d_in[2];
    const float* values_b     = (const float*)d_in[3];
    const float* timestamps_b = (const float*)d_in[4];
    const float* masks_b      = (const float*)d_in[5];
    float* out = (float*)d_out;

    float* aligned = out + OFF_ALIGNED;
    float* maskout = out + OFF_MASK;   // [2,B,R]
    float* idxout  = out + OFF_IDX;    // [2,B,R]
    float* ratio   = out + OFF_RATIO;  // [2,B]

    // Phase 1: fused compaction + search + ratio (256 blocks)
    align_kernel<<<256, 256>>>(timestamps_a, masks_a, timestamps_b, masks_b,
                               maskout, idxout, ratio);

    // Phase 2: gather -> aligned [2,B,C,R]
    gather_kernel<<<1024, 256>>>(values_a, values_b, aligned);

    (void)in_sizes; (void)n_in; (void)out_size;
}